// round 10
// baseline (speedup 1.0000x reference)
#include <cuda_runtime.h>
#include <cuda_fp16.h>
#include <cstdint>

// Problem constants
#define B_ 8
#define S_ 1024
#define D_ 1024
#define M_TOT (B_ * S_)   // 8192

// Scratch (allocation-free rule: __device__ globals)
__device__ float  g_Q[B_ * S_ * D_];
__device__ float  g_K[B_ * S_ * D_];
__device__ float  g_V[B_ * S_ * D_];
__device__ __half g_q16[B_ * S_ * D_];
__device__ __half g_k16[B_ * S_ * D_];
__device__ __half g_v16[B_ * S_ * D_];
__device__ __half g_a16[B_ * S_ * D_];
__device__ __half g_wq16[D_ * D_];
__device__ __half g_wk16[D_ * D_];
__device__ __half g_wv16[D_ * D_];
__device__ __half g_wo16[D_ * D_];

// ---------------------------------------------------------------------------
// Helpers
// ---------------------------------------------------------------------------
__device__ __forceinline__ uint32_t smem_u32(const void* p) {
    uint32_t a;
    asm("{ .reg .u64 t; cvta.to.shared.u64 t, %1; cvt.u32.u64 %0, t; }"
        : "=r"(a) : "l"(p));
    return a;
}

#define LDSM4(r, addr)                                                        \
    asm volatile("ldmatrix.sync.aligned.m8n8.x4.shared.b16 "                  \
                 "{%0, %1, %2, %3}, [%4];"                                    \
                 : "=r"((r)[0]), "=r"((r)[1]), "=r"((r)[2]), "=r"((r)[3])     \
                 : "r"(addr))

#define MMA16816F16(d, a, b)                                                  \
    asm volatile("mma.sync.aligned.m16n8k16.row.col.f32.f16.f16.f32 "         \
                 "{%0, %1, %2, %3}, {%4, %5, %6, %7}, {%8, %9}, "             \
                 "{%0, %1, %2, %3};"                                          \
                 : "+f"((d)[0]), "+f"((d)[1]), "+f"((d)[2]), "+f"((d)[3])     \
                 : "r"((a)[0]), "r"((a)[1]), "r"((a)[2]), "r"((a)[3]),        \
                   "r"((b)[0]), "r"((b)[1]))

#define CP_ASYNC16(dst, src)                                                  \
    asm volatile("cp.async.cg.shared.global [%0], [%1], 16;"                  \
                 :: "r"(dst), "l"(src) : "memory")
#define CP_COMMIT() asm volatile("cp.async.commit_group;" ::: "memory")
#define CP_WAIT2()  asm volatile("cp.async.wait_group 2;" ::: "memory")

// ---------------------------------------------------------------------------
// fp32 -> fp16 pre-conversion (multi-tensor, z-indexed)
// ---------------------------------------------------------------------------
struct CvtArgs { const float4* in[4]; uint2* out[4]; };

__global__ void cvt_multi(CvtArgs a, int n4)
{
    const float4* in = a.in[blockIdx.z];
    uint2* out = a.out[blockIdx.z];
    int i = blockIdx.x * blockDim.x + threadIdx.x;
    if (i < n4) {
        float4 v = in[i];
        uint32_t p01, p23;
        asm("cvt.rn.f16x2.f32 %0, %1, %2;" : "=r"(p01) : "f"(v.y), "f"(v.x));
        asm("cvt.rn.f16x2.f32 %0, %1, %2;" : "=r"(p23) : "f"(v.w), "f"(v.z));
        out[i] = make_uint2(p01, p23);
    }
}

// ---------------------------------------------------------------------------
// fp16 HMMA GEMM (NT), cp.async 4-stage pipeline, 512 threads (16 warps,
// 4m x 4n). BM=BN=128, BK=32, warp tile 32x32. A,W already fp16 in gmem.
// Stage = 2 fp16 tiles, row stride 80B (conflict-free ldmatrix: banks
// 20r mod 32 tile perfectly). wait_group 2 keeps 3 chunks in flight.
// Fragment pipelining: both k-steps' LDSMs issue before any MMA, so the
// second batch's LDS latency hides entirely under the first MMA block.
// ---------------------------------------------------------------------------
#define ROWB 80
#define TILE_B (128 * ROWB)           // 10240 bytes per tile
#define STAGE_B (2 * TILE_B)          // 20480 bytes per stage
#define NSTAGE 4
#define GEMM_SMEM (NSTAGE * STAGE_B)  // 81920 bytes
#define NCH (D_ / 32)                 // 32 chunks

template <int SIG>
__global__ void __launch_bounds__(512) gemm_tc(
    const __half* __restrict__ A, const __half* __restrict__ W,
    const float* __restrict__ bias, float* __restrict__ C)
{
    extern __shared__ __align__(128) char dsm[];
    const uint32_t s0 = smem_u32(dsm);

    const int t    = threadIdx.x;
    const int warp = t >> 5;
    const int lane = t & 31;
    const int bm   = blockIdx.y * 128;
    const int bn   = blockIdx.x * 128;
    const int wm   = (warp & 3) * 32;
    const int wn   = (warp >> 2) * 32;

    // cp.async mapping: one 16B copy per thread per tile
    const int crow = t >> 2;
    const int cseg = t & 3;
    const __half* gA = A + (size_t)(bm + crow) * D_ + cseg * 8;
    const __half* gW = W + (size_t)(bn + crow) * D_ + cseg * 8;
    const uint32_t cdst = (uint32_t)crow * ROWB + cseg * 16;

    // ldmatrix lane addressing
    const uint32_t a_off = (uint32_t)(wm + (lane & 15)) * ROWB + ((lane >> 4) << 4);
    const uint32_t w_off =
        (uint32_t)(wn + ((lane >> 4) << 3) + (lane & 7)) * ROWB + (((lane >> 3) & 1) << 4);

    float acc[2][4][4];
#pragma unroll
    for (int mt = 0; mt < 2; mt++)
#pragma unroll
        for (int nt = 0; nt < 4; nt++)
#pragma unroll
            for (int i = 0; i < 4; i++) acc[mt][nt][i] = 0.f;

    // Prologue: issue chunks 0..2
#pragma unroll
    for (int st = 0; st < NSTAGE - 1; st++) {
        const uint32_t sb = s0 + st * STAGE_B;
        CP_ASYNC16(sb + cdst,          gA + st * 32);
        CP_ASYNC16(sb + TILE_B + cdst, gW + st * 32);
        CP_COMMIT();
    }

#pragma unroll 1
    for (int ch = 0; ch < NCH; ch++) {
        CP_WAIT2();           // chunk ch resident
        __syncthreads();      // visible to all; stage (ch-1)&3 free

        if (ch + NSTAGE - 1 < NCH) {
            const uint32_t sb = s0 + (uint32_t)((ch + NSTAGE - 1) & (NSTAGE - 1)) * STAGE_B;
            CP_ASYNC16(sb + cdst,          gA + (ch + NSTAGE - 1) * 32);
            CP_ASYNC16(sb + TILE_B + cdst, gW + (ch + NSTAGE - 1) * 32);
        }
        CP_COMMIT();

        const uint32_t cur = s0 + (uint32_t)(ch & (NSTAGE - 1)) * STAGE_B;
        const uint32_t cA = cur, cW = cur + TILE_B;

        // All 8 LDSMs (both k-steps) before any MMA
        uint32_t av0[2][4], wv0[2][4], av1[2][4], wv1[2][4];
        LDSM4(av0[0], cA + a_off);
        LDSM4(av0[1], cA + a_off + 16 * ROWB);
        LDSM4(wv0[0], cW + w_off);
        LDSM4(wv0[1], cW + w_off + 16 * ROWB);
        LDSM4(av1[0], cA + a_off + 32);
        LDSM4(av1[1], cA + a_off + 16 * ROWB + 32);
        LDSM4(wv1[0], cW + w_off + 32);
        LDSM4(wv1[1], cW + w_off + 16 * ROWB + 32);

#pragma unroll
        for (int mt = 0; mt < 2; mt++)
#pragma unroll
            for (int nt = 0; nt < 4; nt++)
                MMA16816F16(acc[mt][nt], av0[mt], (&wv0[nt >> 1][(nt & 1) * 2]));
#pragma unroll
        for (int mt = 0; mt < 2; mt++)
#pragma unroll
            for (int nt = 0; nt < 4; nt++)
                MMA16816F16(acc[mt][nt], av1[mt], (&wv1[nt >> 1][(nt & 1) * 2]));
    }

    // Epilogue: direct register -> gmem, bias (+sigmoid)
    const int er0 = bm + wm + (lane >> 2);
    const int ec0 = bn + wn + (lane & 3) * 2;

    float2 bb[4];
#pragma unroll
    for (int nt = 0; nt < 4; nt++)
        bb[nt] = *(const float2*)&bias[ec0 + nt * 8];

#pragma unroll
    for (int mt = 0; mt < 2; mt++) {
#pragma unroll
        for (int nt = 0; nt < 4; nt++) {
#pragma unroll
            for (int h = 0; h < 2; h++) {
                float2 v;
                v.x = acc[mt][nt][h * 2 + 0] + bb[nt].x;
                v.y = acc[mt][nt][h * 2 + 1] + bb[nt].y;
                if (SIG) {
                    v.x = 1.f / (1.f + __expf(-v.x));
                    v.y = 1.f / (1.f + __expf(-v.y));
                }
                *(float2*)(C + (size_t)(er0 + mt * 16 + h * 8) * D_ + ec0 + nt * 8) = v;
            }
        }
    }
}

// ---------------------------------------------------------------------------
// Fused "attention" middle stage (R8 version, proven). 512 threads, b-split
// warp-groups; pass 2 register-tiled 4h x 4p; fp16 output to g_a16.
// ---------------------------------------------------------------------------
#define ES_STRIDE 68
#define ES_PER_B  (64 * ES_STRIDE)
#define VS_PER_B  (16 * ES_STRIDE)
#define V_BASE    4352                       // V region offset inside R
#define SMEM_FLOATS (8 * ES_PER_B + 16384)   // 200 KB

__global__ void __launch_bounds__(512) attn_kernel()
{
    extern __shared__ float smf[];
    float* ES = smf;
    float* R  = smf + 8 * ES_PER_B;

    const int s  = blockIdx.x;
    const int t  = threadIdx.x;
    const int tg = t >> 8;        // warp-group: 0 -> b 0..3, 1 -> b 4..7
    const int tt = t & 255;

    // Load Q,K rows for all 8 batches at this s (coalesced float4)
    for (int f = t; f < 8 * 256; f += 512) {
        const int b  = f >> 8;
        const int d4 = f & 255;
        const size_t g = ((size_t)b * S_ + s) * 256 + d4;
        ((float4*)R)[f]          = ((const float4*)g_Q)[g];
        ((float4*)(R + 8192))[f] = ((const float4*)g_K)[g];
    }
    __syncthreads();

    const float* Qs = R;
    const float* Ks = R + 8192;
    const int tp = (tt >> 4) * 4;
    const int tq = (tt & 15) * 4;
    const int b0 = tg * 4;

    float sacc[4][4];
#pragma unroll
    for (int i = 0; i < 4; i++)
#pragma unroll
        for (int j = 0; j < 4; j++) sacc[i][j] = 0.f;

    // Pass 1: exp-scores for this group's 4 batches, partial denominators
#pragma unroll
    for (int bb = 0; bb < 4; bb++) {
        const int b = b0 + bb;
        const float* Qb = Qs + b * 1024;
        const float* Kb = Ks + b * 1024;
        float acc[4][4];
#pragma unroll
        for (int i = 0; i < 4; i++)
#pragma unroll
            for (int j = 0; j < 4; j++) acc[i][j] = 0.f;

#pragma unroll
        for (int h = 0; h < 16; h++) {
            float4 q4 = *(const float4*)(Qb + h * 64 + tp);
            float4 k4 = *(const float4*)(Kb + h * 64 + tq);
            float qa[4] = {q4.x, q4.y, q4.z, q4.w};
            float ka[4] = {k4.x, k4.y, k4.z, k4.w};
#pragma unroll
            for (int i = 0; i < 4; i++)
#pragma unroll
                for (int j = 0; j < 4; j++)
                    acc[i][j] += qa[i] * ka[j];
        }
        float* ESb = ES + b * ES_PER_B;
#pragma unroll
        for (int i = 0; i < 4; i++) {
            float4 e;
            e.x = __expf(acc[i][0] * 0.125f);
            e.y = __expf(acc[i][1] * 0.125f);
            e.z = __expf(acc[i][2] * 0.125f);
            e.w = __expf(acc[i][3] * 0.125f);
            sacc[i][0] += e.x; sacc[i][1] += e.y;
            sacc[i][2] += e.z; sacc[i][3] += e.w;
            *(float4*)&ESb[(tp + i) * ES_STRIDE + tq] = e;
        }
    }
    __syncthreads();   // Q/K reads done; R reusable as exchange strip

    // Denominator exchange between the two groups via P = R[0..4351]
    float* P = R;
    if (tg == 0) {
#pragma unroll
        for (int i = 0; i < 4; i++)
            *(float4*)&P[(tp + i) * ES_STRIDE + tq] =
                make_float4(sacc[i][0], sacc[i][1], sacc[i][2], sacc[i][3]);
    }
    __syncthreads();

    float rd[4][4];
    if (tg == 1) {
#pragma unroll
        for (int i = 0; i < 4; i++) {
            float4 o = *(const float4*)&P[(tp + i) * ES_STRIDE + tq];
            rd[i][0] = 1.f / (o.x + sacc[i][0]);
            rd[i][1] = 1.f / (o.y + sacc[i][1]);
            rd[i][2] = 1.f / (o.z + sacc[i][2]);
            rd[i][3] = 1.f / (o.w + sacc[i][3]);
        }
        __syncthreads();
#pragma unroll
        for (int i = 0; i < 4; i++)
            *(float4*)&P[(tp + i) * ES_STRIDE + tq] =
                make_float4(rd[i][0], rd[i][1], rd[i][2], rd[i][3]);
    } else {
        __syncthreads();
    }
    __syncthreads();
    if (tg == 0) {
#pragma unroll
        for (int i = 0; i < 4; i++) {
            float4 r4 = *(const float4*)&P[(tp + i) * ES_STRIDE + tq];
            rd[i][0] = r4.x; rd[i][1] = r4.y; rd[i][2] = r4.z; rd[i][3] = r4.w;
        }
    }

    // Normalize this group's ES in place
#pragma unroll
    for (int bb = 0; bb < 4; bb++) {
        float* ESb = ES + (b0 + bb) * ES_PER_B;
#pragma unroll
        for (int i = 0; i < 4; i++) {
            float4 e = *(const float4*)&ESb[(tp + i) * ES_STRIDE + tq];
            e.x *= rd[i][0]; e.y *= rd[i][1];
            e.z *= rd[i][2]; e.w *= rd[i][3];
            *(float4*)&ESb[(tp + i) * ES_STRIDE + tq] = e;
        }
    }
    __syncthreads();   // rd reads from P done -> V may overwrite R

    // Load V (stride-68 padded layout at R + V_BASE)
    for (int f = t; f < 8 * 256; f += 512) {
        const int b  = f >> 8;
        const int d4 = f & 255;
        const size_t g = ((size_t)b * S_ + s) * 256 + d4;
        float4 v = ((const float4*)g_V)[g];
        const int d = d4 * 4;
        const int h = d >> 6;
        const int q = d & 63;
        float* Vb = R + V_BASE + b * VS_PER_B + h * ES_STRIDE + q;
        Vb[0] = v.x; Vb[1] = v.y; Vb[2] = v.z; Vb[3] = v.w;
    }
    __syncthreads();

    // Pass 2 register-tiled: 64 threads per b, each computes 4h x 4p outputs.
    {
        const int bsel = tt >> 6;
        const int u    = tt & 63;
        const int lp   = u & 15;
        const int lh   = u >> 4;
        const int b    = b0 + bsel;
        const float* ESb = ES + b * ES_PER_B;
        const float* Vb  = R + V_BASE + b * VS_PER_B;

        float oacc[4][4];
#pragma unroll
        for (int i = 0; i < 4; i++)
#pragma unroll
            for (int j = 0; j < 4; j++) oacc[i][j] = 0.f;

#pragma unroll
        for (int q = 0; q < 64; q += 4) {
            float4 e4[4], v4[4];
#pragma unroll
            for (int pp = 0; pp < 4; pp++)
                e4[pp] = *(const float4*)&ESb[(lp + 16 * pp) * ES_STRIDE + q];
#pragma unroll
            for (int hh = 0; hh < 4; hh++)
                v4[hh] = *(const float4*)&Vb[(lh + 4 * hh) * ES_STRIDE + q];
#pragma unroll
            for (int hh = 0; hh < 4; hh++)
#pragma unroll
                for (int pp = 0; pp < 4; pp++)
                    oacc[hh][pp] += e4[pp].x * v4[hh].x + e4[pp].y * v4[hh].y +
                                    e4[pp].z * v4[hh].z + e4[pp].w * v4[hh].w;
        }

        __half* ob = g_a16 + ((size_t)b * S_ + s) * D_;
#pragma unroll
        for (int hh = 0; hh < 4; hh++)
#pragma unroll
            for (int pp = 0; pp < 4; pp++)
                ob[(lh + 4 * hh) * 64 + lp + 16 * pp] = __float2half(oacc[hh][pp]);
    }
}

// ---------------------------------------------------------------------------
extern "C" void kernel_launch(void* const* d_in, const int* in_sizes, int n_in,
                              void* d_out, int out_size)
{
    const float* query = (const float*)d_in[0];
    const float* key   = (const float*)d_in[1];
    const float* value = (const float*)d_in[2];
    const float* Wq    = (const float*)d_in[3];
    const float* bq    = (const float*)d_in[4];
    const float* Wk    = (const float*)d_in[5];
    const float* bk    = (const float*)d_in[6];
    const float* Wv    = (const float*)d_in[7];
    const float* bv    = (const float*)d_in[8];
    const float* Wo    = (const float*)d_in[9];
    const float* bo    = (const float*)d_in[10];
    float* out = (float*)d_out;

    float *gQ, *gK, *gV;
    __half *q16, *k16, *v16, *a16, *wq16, *wk16, *wv16, *wo16;
    cudaGetSymbolAddress((void**)&gQ, g_Q);
    cudaGetSymbolAddress((void**)&gK, g_K);
    cudaGetSymbolAddress((void**)&gV, g_V);
    cudaGetSymbolAddress((void**)&q16, g_q16);
    cudaGetSymbolAddress((void**)&k16, g_k16);
    cudaGetSymbolAddress((void**)&v16, g_v16);
    cudaGetSymbolAddress((void**)&a16, g_a16);
    cudaGetSymbolAddress((void**)&wq16, g_wq16);
    cudaGetSymbolAddress((void**)&wk16, g_wk16);
    cudaGetSymbolAddress((void**)&wv16, g_wv16);
    cudaGetSymbolAddress((void**)&wo16, g_wo16);

    // Fused pre-conversion: 3 inputs in one launch, 4 weights in another
    const int nIn4 = (M_TOT * D_) / 4;
    const int nW4  = (D_ * D_) / 4;
    {
        CvtArgs a{};
        a.in[0] = (const float4*)query; a.out[0] = (uint2*)q16;
        a.in[1] = (const float4*)key;   a.out[1] = (uint2*)k16;
        a.in[2] = (const float4*)value; a.out[2] = (uint2*)v16;
        dim3 g((nIn4 + 255) / 256, 1, 3);
        cvt_multi<<<g, 256>>>(a, nIn4);
    }
    {
        CvtArgs a{};
        a.in[0] = (const float4*)Wq; a.out[0] = (uint2*)wq16;
        a.in[1] = (const float4*)Wk; a.out[1] = (uint2*)wk16;
        a.in[2] = (const float4*)Wv; a.out[2] = (uint2*)wv16;
        a.in[3] = (const float4*)Wo; a.out[3] = (uint2*)wo16;
        dim3 g((nW4 + 255) / 256, 1, 4);
        cvt_multi<<<g, 256>>>(a, nW4);
    }

    cudaFuncSetAttribute(gemm_tc<0>,
                         cudaFuncAttributeMaxDynamicSharedMemorySize, GEMM_SMEM);
    cudaFuncSetAttribute(gemm_tc<1>,
                         cudaFuncAttributeMaxDynamicSharedMemorySize, GEMM_SMEM);
    cudaFuncSetAttribute(attn_kernel,
                         cudaFuncAttributeMaxDynamicSharedMemorySize,
                         SMEM_FLOATS * 4);

    dim3 grid(D_ / 128, M_TOT / 128);   // (8, 64)
    gemm_tc<0><<<grid, 512, GEMM_SMEM>>>(q16, wq16, bq, gQ);
    gemm_tc<0><<<grid, 512, GEMM_SMEM>>>(k16, wk16, bk, gK);
    gemm_tc<0><<<grid, 512, GEMM_SMEM>>>(v16, wv16, bv, gV);

    attn_kernel<<<S_, 512, SMEM_FLOATS * 4>>>();

    gemm_tc<1><<<grid, 512, GEMM_SMEM>>>(a16, wo16, bo, out);
}

// round 11
// speedup vs baseline: 1.1267x; 1.1267x over previous
#include <cuda_runtime.h>
#include <cuda_fp16.h>
#include <cstdint>

// Problem constants
#define B_ 8
#define S_ 1024
#define D_ 1024
#define M_TOT (B_ * S_)   // 8192

// Scratch (allocation-free rule: __device__ globals)
__device__ float  g_Q[B_ * S_ * D_];
__device__ float  g_K[B_ * S_ * D_];
__device__ float  g_V[B_ * S_ * D_];
__device__ __half g_q16[B_ * S_ * D_];
__device__ __half g_k16[B_ * S_ * D_];
__device__ __half g_v16[B_ * S_ * D_];
__device__ __half g_a16[B_ * S_ * D_];
__device__ __half g_wq16[D_ * D_];
__device__ __half g_wk16[D_ * D_];
__device__ __half g_wv16[D_ * D_];
__device__ __half g_wo16[D_ * D_];

// ---------------------------------------------------------------------------
// Helpers
// ---------------------------------------------------------------------------
__device__ __forceinline__ uint32_t smem_u32(const void* p) {
    uint32_t a;
    asm("{ .reg .u64 t; cvta.to.shared.u64 t, %1; cvt.u32.u64 %0, t; }"
        : "=r"(a) : "l"(p));
    return a;
}

#define LDSM4(r, addr)                                                        \
    asm volatile("ldmatrix.sync.aligned.m8n8.x4.shared.b16 "                  \
                 "{%0, %1, %2, %3}, [%4];"                                    \
                 : "=r"((r)[0]), "=r"((r)[1]), "=r"((r)[2]), "=r"((r)[3])     \
                 : "r"(addr))

#define MMA16816F16(d, a, b)                                                  \
    asm volatile("mma.sync.aligned.m16n8k16.row.col.f32.f16.f16.f32 "         \
                 "{%0, %1, %2, %3}, {%4, %5, %6, %7}, {%8, %9}, "             \
                 "{%0, %1, %2, %3};"                                          \
                 : "+f"((d)[0]), "+f"((d)[1]), "+f"((d)[2]), "+f"((d)[3])     \
                 : "r"((a)[0]), "r"((a)[1]), "r"((a)[2]), "r"((a)[3]),        \
                   "r"((b)[0]), "r"((b)[1]))

#define CP_ASYNC16(dst, src)                                                  \
    asm volatile("cp.async.cg.shared.global [%0], [%1], 16;"                  \
                 :: "r"(dst), "l"(src) : "memory")
#define CP_COMMIT() asm volatile("cp.async.commit_group;" ::: "memory")
#define CP_WAIT2()  asm volatile("cp.async.wait_group 2;" ::: "memory")

// ---------------------------------------------------------------------------
// fp32 -> fp16 pre-conversion (simple per-tensor kernel; NO param arrays —
// dynamic indexing of by-value param structs spills to local memory)
// ---------------------------------------------------------------------------
__global__ void cvt16(const float4* __restrict__ in, uint2* __restrict__ out,
                      int n4)
{
    int i = blockIdx.x * blockDim.x + threadIdx.x;
    if (i < n4) {
        float4 v = in[i];
        uint32_t p01, p23;
        asm("cvt.rn.f16x2.f32 %0, %1, %2;" : "=r"(p01) : "f"(v.y), "f"(v.x));
        asm("cvt.rn.f16x2.f32 %0, %1, %2;" : "=r"(p23) : "f"(v.w), "f"(v.z));
        out[i] = make_uint2(p01, p23);
    }
}

// ---------------------------------------------------------------------------
// fp16 HMMA GEMM body (NT), cp.async 4-stage pipeline, 512 threads (16 warps,
// 4m x 4n). BM=BN=128, BK=32, warp tile 32x32. Stage = 2 fp16 tiles,
// row stride 80B (conflict-free ldmatrix: banks 20r mod 32 tile perfectly).
// wait_group 2 keeps 3 chunks in flight. Fragment pipelining: both k-steps'
// LDSMs issue before any MMA (measured win R10: 72 -> 68.3 us).
// ---------------------------------------------------------------------------
#define ROWB 80
#define TILE_B (128 * ROWB)           // 10240 bytes per tile
#define STAGE_B (2 * TILE_B)          // 20480 bytes per stage
#define NSTAGE 4
#define GEMM_SMEM (NSTAGE * STAGE_B)  // 81920 bytes
#define NCH (D_ / 32)                 // 32 chunks

template <int SIG>
__device__ __forceinline__ void gemm_body(
    const __half* __restrict__ A, const __half* __restrict__ W,
    const float* __restrict__ bias, float* __restrict__ C, char* dsm)
{
    const uint32_t s0 = smem_u32(dsm);

    const int t    = threadIdx.x;
    const int warp = t >> 5;
    const int lane = t & 31;
    const int bm   = blockIdx.y * 128;
    const int bn   = blockIdx.x * 128;
    const int wm   = (warp & 3) * 32;
    const int wn   = (warp >> 2) * 32;

    // cp.async mapping: one 16B copy per thread per tile
    const int crow = t >> 2;
    const int cseg = t & 3;
    const __half* gA = A + (size_t)(bm + crow) * D_ + cseg * 8;
    const __half* gW = W + (size_t)(bn + crow) * D_ + cseg * 8;
    const uint32_t cdst = (uint32_t)crow * ROWB + cseg * 16;

    // ldmatrix lane addressing
    const uint32_t a_off = (uint32_t)(wm + (lane & 15)) * ROWB + ((lane >> 4) << 4);
    const uint32_t w_off =
        (uint32_t)(wn + ((lane >> 4) << 3) + (lane & 7)) * ROWB + (((lane >> 3) & 1) << 4);

    float acc[2][4][4];
#pragma unroll
    for (int mt = 0; mt < 2; mt++)
#pragma unroll
        for (int nt = 0; nt < 4; nt++)
#pragma unroll
            for (int i = 0; i < 4; i++) acc[mt][nt][i] = 0.f;

    // Prologue: issue chunks 0..2
#pragma unroll
    for (int st = 0; st < NSTAGE - 1; st++) {
        const uint32_t sb = s0 + st * STAGE_B;
        CP_ASYNC16(sb + cdst,          gA + st * 32);
        CP_ASYNC16(sb + TILE_B + cdst, gW + st * 32);
        CP_COMMIT();
    }

#pragma unroll 1
    for (int ch = 0; ch < NCH; ch++) {
        CP_WAIT2();           // chunk ch resident
        __syncthreads();      // visible to all; stage (ch-1)&3 free

        if (ch + NSTAGE - 1 < NCH) {
            const uint32_t sb = s0 + (uint32_t)((ch + NSTAGE - 1) & (NSTAGE - 1)) * STAGE_B;
            CP_ASYNC16(sb + cdst,          gA + (ch + NSTAGE - 1) * 32);
            CP_ASYNC16(sb + TILE_B + cdst, gW + (ch + NSTAGE - 1) * 32);
        }
        CP_COMMIT();

        const uint32_t cur = s0 + (uint32_t)(ch & (NSTAGE - 1)) * STAGE_B;
        const uint32_t cA = cur, cW = cur + TILE_B;

        // All 8 LDSMs (both k-steps) before any MMA
        uint32_t av0[2][4], wv0[2][4], av1[2][4], wv1[2][4];
        LDSM4(av0[0], cA + a_off);
        LDSM4(av0[1], cA + a_off + 16 * ROWB);
        LDSM4(wv0[0], cW + w_off);
        LDSM4(wv0[1], cW + w_off + 16 * ROWB);
        LDSM4(av1[0], cA + a_off + 32);
        LDSM4(av1[1], cA + a_off + 16 * ROWB + 32);
        LDSM4(wv1[0], cW + w_off + 32);
        LDSM4(wv1[1], cW + w_off + 16 * ROWB + 32);

#pragma unroll
        for (int mt = 0; mt < 2; mt++)
#pragma unroll
            for (int nt = 0; nt < 4; nt++)
                MMA16816F16(acc[mt][nt], av0[mt], (&wv0[nt >> 1][(nt & 1) * 2]));
#pragma unroll
        for (int mt = 0; mt < 2; mt++)
#pragma unroll
            for (int nt = 0; nt < 4; nt++)
                MMA16816F16(acc[mt][nt], av1[mt], (&wv1[nt >> 1][(nt & 1) * 2]));
    }

    // Epilogue: direct register -> gmem, bias (+sigmoid)
    const int er0 = bm + wm + (lane >> 2);
    const int ec0 = bn + wn + (lane & 3) * 2;

    float2 bb[4];
#pragma unroll
    for (int nt = 0; nt < 4; nt++)
        bb[nt] = *(const float2*)&bias[ec0 + nt * 8];

#pragma unroll
    for (int mt = 0; mt < 2; mt++) {
#pragma unroll
        for (int nt = 0; nt < 4; nt++) {
#pragma unroll
            for (int h = 0; h < 2; h++) {
                float2 v;
                v.x = acc[mt][nt][h * 2 + 0] + bb[nt].x;
                v.y = acc[mt][nt][h * 2 + 1] + bb[nt].y;
                if (SIG) {
                    v.x = 1.f / (1.f + __expf(-v.x));
                    v.y = 1.f / (1.f + __expf(-v.y));
                }
                *(float2*)(C + (size_t)(er0 + mt * 16 + h * 8) * D_ + ec0 + nt * 8) = v;
            }
        }
    }
}

// Merged Q/K/V projection: blockIdx.z selects the operand set via UNIFORM
// ternaries on scalar params (no param-array indexing -> no local spill).
__global__ void __launch_bounds__(512) gemm_qkv(
    const __half* A0, const __half* W0, const float* b0, float* C0,
    const __half* A1, const __half* W1, const float* b1, float* C1,
    const __half* A2, const __half* W2, const float* b2, float* C2)
{
    extern __shared__ __align__(128) char dsm[];
    const unsigned z = blockIdx.z;
    const __half* A = (z == 0) ? A0 : (z == 1) ? A1 : A2;
    const __half* W = (z == 0) ? W0 : (z == 1) ? W1 : W2;
    const float*  b = (z == 0) ? b0 : (z == 1) ? b1 : b2;
    float*        C = (z == 0) ? C0 : (z == 1) ? C1 : C2;
    gemm_body<0>(A, W, b, C, dsm);
}

__global__ void __launch_bounds__(512) gemm_o(
    const __half* __restrict__ A, const __half* __restrict__ W,
    const float* __restrict__ bias, float* __restrict__ C)
{
    extern __shared__ __align__(128) char dsm[];
    gemm_body<1>(A, W, bias, C, dsm);
}

// ---------------------------------------------------------------------------
// Fused "attention" middle stage (R8 version, proven). 512 threads, b-split
// warp-groups; pass 2 register-tiled 4h x 4p; fp16 output to g_a16.
// ---------------------------------------------------------------------------
#define ES_STRIDE 68
#define ES_PER_B  (64 * ES_STRIDE)
#define VS_PER_B  (16 * ES_STRIDE)
#define V_BASE    4352                       // V region offset inside R
#define SMEM_FLOATS (8 * ES_PER_B + 16384)   // 200 KB

__global__ void __launch_bounds__(512) attn_kernel()
{
    extern __shared__ float smf[];
    float* ES = smf;
    float* R  = smf + 8 * ES_PER_B;

    const int s  = blockIdx.x;
    const int t  = threadIdx.x;
    const int tg = t >> 8;        // warp-group: 0 -> b 0..3, 1 -> b 4..7
    const int tt = t & 255;

    // Load Q,K rows for all 8 batches at this s (coalesced float4)
    for (int f = t; f < 8 * 256; f += 512) {
        const int b  = f >> 8;
        const int d4 = f & 255;
        const size_t g = ((size_t)b * S_ + s) * 256 + d4;
        ((float4*)R)[f]          = ((const float4*)g_Q)[g];
        ((float4*)(R + 8192))[f] = ((const float4*)g_K)[g];
    }
    __syncthreads();

    const float* Qs = R;
    const float* Ks = R + 8192;
    const int tp = (tt >> 4) * 4;
    const int tq = (tt & 15) * 4;
    const int b0 = tg * 4;

    float sacc[4][4];
#pragma unroll
    for (int i = 0; i < 4; i++)
#pragma unroll
        for (int j = 0; j < 4; j++) sacc[i][j] = 0.f;

    // Pass 1: exp-scores for this group's 4 batches, partial denominators
#pragma unroll
    for (int bb = 0; bb < 4; bb++) {
        const int b = b0 + bb;
        const float* Qb = Qs + b * 1024;
        const float* Kb = Ks + b * 1024;
        float acc[4][4];
#pragma unroll
        for (int i = 0; i < 4; i++)
#pragma unroll
            for (int j = 0; j < 4; j++) acc[i][j] = 0.f;

#pragma unroll
        for (int h = 0; h < 16; h++) {
            float4 q4 = *(const float4*)(Qb + h * 64 + tp);
            float4 k4 = *(const float4*)(Kb + h * 64 + tq);
            float qa[4] = {q4.x, q4.y, q4.z, q4.w};
            float ka[4] = {k4.x, k4.y, k4.z, k4.w};
#pragma unroll
            for (int i = 0; i < 4; i++)
#pragma unroll
                for (int j = 0; j < 4; j++)
                    acc[i][j] += qa[i] * ka[j];
        }
        float* ESb = ES + b * ES_PER_B;
#pragma unroll
        for (int i = 0; i < 4; i++) {
            float4 e;
            e.x = __expf(acc[i][0] * 0.125f);
            e.y = __expf(acc[i][1] * 0.125f);
            e.z = __expf(acc[i][2] * 0.125f);
            e.w = __expf(acc[i][3] * 0.125f);
            sacc[i][0] += e.x; sacc[i][1] += e.y;
            sacc[i][2] += e.z; sacc[i][3] += e.w;
            *(float4*)&ESb[(tp + i) * ES_STRIDE + tq] = e;
        }
    }
    __syncthreads();   // Q/K reads done; R reusable as exchange strip

    // Denominator exchange between the two groups via P = R[0..4351]
    float* P = R;
    if (tg == 0) {
#pragma unroll
        for (int i = 0; i < 4; i++)
            *(float4*)&P[(tp + i) * ES_STRIDE + tq] =
                make_float4(sacc[i][0], sacc[i][1], sacc[i][2], sacc[i][3]);
    }
    __syncthreads();

    float rd[4][4];
    if (tg == 1) {
#pragma unroll
        for (int i = 0; i < 4; i++) {
            float4 o = *(const float4*)&P[(tp + i) * ES_STRIDE + tq];
            rd[i][0] = 1.f / (o.x + sacc[i][0]);
            rd[i][1] = 1.f / (o.y + sacc[i][1]);
            rd[i][2] = 1.f / (o.z + sacc[i][2]);
            rd[i][3] = 1.f / (o.w + sacc[i][3]);
        }
        __syncthreads();
#pragma unroll
        for (int i = 0; i < 4; i++)
            *(float4*)&P[(tp + i) * ES_STRIDE + tq] =
                make_float4(rd[i][0], rd[i][1], rd[i][2], rd[i][3]);
    } else {
        __syncthreads();
    }
    __syncthreads();
    if (tg == 0) {
#pragma unroll
        for (int i = 0; i < 4; i++) {
            float4 r4 = *(const float4*)&P[(tp + i) * ES_STRIDE + tq];
            rd[i][0] = r4.x; rd[i][1] = r4.y; rd[i][2] = r4.z; rd[i][3] = r4.w;
        }
    }

    // Normalize this group's ES in place
#pragma unroll
    for (int bb = 0; bb < 4; bb++) {
        float* ESb = ES + (b0 + bb) * ES_PER_B;
#pragma unroll
        for (int i = 0; i < 4; i++) {
            float4 e = *(const float4*)&ESb[(tp + i) * ES_STRIDE + tq];
            e.x *= rd[i][0]; e.y *= rd[i][1];
            e.z *= rd[i][2]; e.w *= rd[i][3];
            *(float4*)&ESb[(tp + i) * ES_STRIDE + tq] = e;
        }
    }
    __syncthreads();   // rd reads from P done -> V may overwrite R

    // Load V (stride-68 padded layout at R + V_BASE)
    for (int f = t; f < 8 * 256; f += 512) {
        const int b  = f >> 8;
        const int d4 = f & 255;
        const size_t g = ((size_t)b * S_ + s) * 256 + d4;
        float4 v = ((const float4*)g_V)[g];
        const int d = d4 * 4;
        const int h = d >> 6;
        const int q = d & 63;
        float* Vb = R + V_BASE + b * VS_PER_B + h * ES_STRIDE + q;
        Vb[0] = v.x; Vb[1] = v.y; Vb[2] = v.z; Vb[3] = v.w;
    }
    __syncthreads();

    // Pass 2 register-tiled: 64 threads per b, each computes 4h x 4p outputs.
    {
        const int bsel = tt >> 6;
        const int u    = tt & 63;
        const int lp   = u & 15;
        const int lh   = u >> 4;
        const int b    = b0 + bsel;
        const float* ESb = ES + b * ES_PER_B;
        const float* Vb  = R + V_BASE + b * VS_PER_B;

        float oacc[4][4];
#pragma unroll
        for (int i = 0; i < 4; i++)
#pragma unroll
            for (int j = 0; j < 4; j++) oacc[i][j] = 0.f;

#pragma unroll
        for (int q = 0; q < 64; q += 4) {
            float4 e4[4], v4[4];
#pragma unroll
            for (int pp = 0; pp < 4; pp++)
                e4[pp] = *(const float4*)&ESb[(lp + 16 * pp) * ES_STRIDE + q];
#pragma unroll
            for (int hh = 0; hh < 4; hh++)
                v4[hh] = *(const float4*)&Vb[(lh + 4 * hh) * ES_STRIDE + q];
#pragma unroll
            for (int hh = 0; hh < 4; hh++)
#pragma unroll
                for (int pp = 0; pp < 4; pp++)
                    oacc[hh][pp] += e4[pp].x * v4[hh].x + e4[pp].y * v4[hh].y +
                                    e4[pp].z * v4[hh].z + e4[pp].w * v4[hh].w;
        }

        __half* ob = g_a16 + ((size_t)b * S_ + s) * D_;
#pragma unroll
        for (int hh = 0; hh < 4; hh++)
#pragma unroll
            for (int pp = 0; pp < 4; pp++)
                ob[(lh + 4 * hh) * 64 + lp + 16 * pp] = __float2half(oacc[hh][pp]);
    }
}

// ---------------------------------------------------------------------------
extern "C" void kernel_launch(void* const* d_in, const int* in_sizes, int n_in,
                              void* d_out, int out_size)
{
    const float* query = (const float*)d_in[0];
    const float* key   = (const float*)d_in[1];
    const float* value = (const float*)d_in[2];
    const float* Wq    = (const float*)d_in[3];
    const float* bq    = (const float*)d_in[4];
    const float* Wk    = (const float*)d_in[5];
    const float* bk    = (const float*)d_in[6];
    const float* Wv    = (const float*)d_in[7];
    const float* bv    = (const float*)d_in[8];
    const float* Wo    = (const float*)d_in[9];
    const float* bo    = (const float*)d_in[10];
    float* out = (float*)d_out;

    float *gQ, *gK, *gV;
    __half *q16, *k16, *v16, *a16, *wq16, *wk16, *wv16, *wo16;
    cudaGetSymbolAddress((void**)&gQ, g_Q);
    cudaGetSymbolAddress((void**)&gK, g_K);
    cudaGetSymbolAddress((void**)&gV, g_V);
    cudaGetSymbolAddress((void**)&q16, g_q16);
    cudaGetSymbolAddress((void**)&k16, g_k16);
    cudaGetSymbolAddress((void**)&v16, g_v16);
    cudaGetSymbolAddress((void**)&a16, g_a16);
    cudaGetSymbolAddress((void**)&wq16, g_wq16);
    cudaGetSymbolAddress((void**)&wk16, g_wk16);
    cudaGetSymbolAddress((void**)&wv16, g_wv16);
    cudaGetSymbolAddress((void**)&wo16, g_wo16);

    // Pre-convert inputs + weights to fp16 (separate launches, no spills)
    const int nIn4 = (M_TOT * D_) / 4;
    const int nW4  = (D_ * D_) / 4;
    cvt16<<<(nIn4 + 255) / 256, 256>>>((const float4*)query, (uint2*)q16, nIn4);
    cvt16<<<(nIn4 + 255) / 256, 256>>>((const float4*)key,   (uint2*)k16, nIn4);
    cvt16<<<(nIn4 + 255) / 256, 256>>>((const float4*)value, (uint2*)v16, nIn4);
    cvt16<<<(nW4 + 255) / 256, 256>>>((const float4*)Wq, (uint2*)wq16, nW4);
    cvt16<<<(nW4 + 255) / 256, 256>>>((const float4*)Wk, (uint2*)wk16, nW4);
    cvt16<<<(nW4 + 255) / 256, 256>>>((const float4*)Wv, (uint2*)wv16, nW4);
    cvt16<<<(nW4 + 255) / 256, 256>>>((const float4*)Wo, (uint2*)wo16, nW4);

    cudaFuncSetAttribute(gemm_qkv,
                         cudaFuncAttributeMaxDynamicSharedMemorySize, GEMM_SMEM);
    cudaFuncSetAttribute(gemm_o,
                         cudaFuncAttributeMaxDynamicSharedMemorySize, GEMM_SMEM);
    cudaFuncSetAttribute(attn_kernel,
                         cudaFuncAttributeMaxDynamicSharedMemorySize,
                         SMEM_FLOATS * 4);

    // Merged Q/K/V projection (1536 CTAs: one tail instead of three)
    {
        dim3 grid(D_ / 128, M_TOT / 128, 3);   // (8, 64, 3)
        gemm_qkv<<<grid, 512, GEMM_SMEM>>>(
            q16, wq16, bq, gQ,
            k16, wk16, bk, gK,
            v16, wv16, bv, gV);
    }

    attn_kernel<<<S_, 512, SMEM_FLOATS * 4>>>();

    {
        dim3 grid(D_ / 128, M_TOT / 128);      // (8, 64)
        gemm_o<<<grid, 512, GEMM_SMEM>>>(a16, wo16, bo, out);
    }
}

// round 12
// speedup vs baseline: 1.2148x; 1.0782x over previous
#include <cuda_runtime.h>
#include <cuda_fp16.h>
#include <cstdint>

// Problem constants
#define B_ 8
#define S_ 1024
#define D_ 1024
#define M_TOT (B_ * S_)   // 8192

// Scratch (allocation-free rule: __device__ globals)
// g_Q/g_K/g_V sized as float but used as fp16 (half the space) this round.
__device__ float  g_Q[B_ * S_ * D_];
__device__ float  g_K[B_ * S_ * D_];
__device__ float  g_V[B_ * S_ * D_];
__device__ __half g_q16[B_ * S_ * D_];
__device__ __half g_k16[B_ * S_ * D_];
__device__ __half g_v16[B_ * S_ * D_];
__device__ __half g_a16[B_ * S_ * D_];
__device__ __half g_wq16[D_ * D_];
__device__ __half g_wk16[D_ * D_];
__device__ __half g_wv16[D_ * D_];
__device__ __half g_wo16[D_ * D_];

// ---------------------------------------------------------------------------
// Helpers
// ---------------------------------------------------------------------------
__device__ __forceinline__ uint32_t smem_u32(const void* p) {
    uint32_t a;
    asm("{ .reg .u64 t; cvta.to.shared.u64 t, %1; cvt.u32.u64 %0, t; }"
        : "=r"(a) : "l"(p));
    return a;
}

__device__ __forceinline__ float2 h2f(uint32_t h) {
    __half2 hh = *(__half2*)&h;
    return __half22float2(hh);
}
__device__ __forceinline__ uint32_t f2h(float lo, float hi) {
    uint32_t r;
    asm("cvt.rn.f16x2.f32 %0, %1, %2;" : "=r"(r) : "f"(hi), "f"(lo));
    return r;
}

#define LDSM4(r, addr)                                                        \
    asm volatile("ldmatrix.sync.aligned.m8n8.x4.shared.b16 "                  \
                 "{%0, %1, %2, %3}, [%4];"                                    \
                 : "=r"((r)[0]), "=r"((r)[1]), "=r"((r)[2]), "=r"((r)[3])     \
                 : "r"(addr))

#define MMA16816F16(d, a, b)                                                  \
    asm volatile("mma.sync.aligned.m16n8k16.row.col.f32.f16.f16.f32 "         \
                 "{%0, %1, %2, %3}, {%4, %5, %6, %7}, {%8, %9}, "             \
                 "{%0, %1, %2, %3};"                                          \
                 : "+f"((d)[0]), "+f"((d)[1]), "+f"((d)[2]), "+f"((d)[3])     \
                 : "r"((a)[0]), "r"((a)[1]), "r"((a)[2]), "r"((a)[3]),        \
                   "r"((b)[0]), "r"((b)[1]))

#define CP_ASYNC16(dst, src)                                                  \
    asm volatile("cp.async.cg.shared.global [%0], [%1], 16;"                  \
                 :: "r"(dst), "l"(src) : "memory")
#define CP_COMMIT() asm volatile("cp.async.commit_group;" ::: "memory")
#define CP_WAIT2()  asm volatile("cp.async.wait_group 2;" ::: "memory")

// ---------------------------------------------------------------------------
// fp32 -> fp16 pre-conversion (simple per-tensor kernel; no param arrays)
// ---------------------------------------------------------------------------
__global__ void cvt16(const float4* __restrict__ in, uint2* __restrict__ out,
                      int n4)
{
    int i = blockIdx.x * blockDim.x + threadIdx.x;
    if (i < n4) {
        float4 v = in[i];
        out[i] = make_uint2(f2h(v.x, v.y), f2h(v.z, v.w));
    }
}

// ---------------------------------------------------------------------------
// fp16 HMMA GEMM body (NT), cp.async 4-stage pipeline, 512 threads (16 warps,
// 4m x 4n). BM=BN=128, BK=32, warp tile 32x32. Stage = 2 fp16 tiles,
// row stride 80B (conflict-free ldmatrix). Fragment pipelining (R10 win).
// SIG=0: writes __half output (attn consumes fp16). SIG=1: fp32 + sigmoid.
// ---------------------------------------------------------------------------
#define ROWB 80
#define TILE_B (128 * ROWB)
#define STAGE_B (2 * TILE_B)
#define NSTAGE 4
#define GEMM_SMEM (NSTAGE * STAGE_B)  // 81920 bytes
#define NCH (D_ / 32)

template <int SIG>
__device__ __forceinline__ void gemm_body(
    const __half* __restrict__ A, const __half* __restrict__ W,
    const float* __restrict__ bias, void* __restrict__ Cv, char* dsm)
{
    const uint32_t s0 = smem_u32(dsm);

    const int t    = threadIdx.x;
    const int warp = t >> 5;
    const int lane = t & 31;
    const int bm   = blockIdx.y * 128;
    const int bn   = blockIdx.x * 128;
    const int wm   = (warp & 3) * 32;
    const int wn   = (warp >> 2) * 32;

    const int crow = t >> 2;
    const int cseg = t & 3;
    const __half* gA = A + (size_t)(bm + crow) * D_ + cseg * 8;
    const __half* gW = W + (size_t)(bn + crow) * D_ + cseg * 8;
    const uint32_t cdst = (uint32_t)crow * ROWB + cseg * 16;

    const uint32_t a_off = (uint32_t)(wm + (lane & 15)) * ROWB + ((lane >> 4) << 4);
    const uint32_t w_off =
        (uint32_t)(wn + ((lane >> 4) << 3) + (lane & 7)) * ROWB + (((lane >> 3) & 1) << 4);

    float acc[2][4][4];
#pragma unroll
    for (int mt = 0; mt < 2; mt++)
#pragma unroll
        for (int nt = 0; nt < 4; nt++)
#pragma unroll
            for (int i = 0; i < 4; i++) acc[mt][nt][i] = 0.f;

#pragma unroll
    for (int st = 0; st < NSTAGE - 1; st++) {
        const uint32_t sb = s0 + st * STAGE_B;
        CP_ASYNC16(sb + cdst,          gA + st * 32);
        CP_ASYNC16(sb + TILE_B + cdst, gW + st * 32);
        CP_COMMIT();
    }

#pragma unroll 1
    for (int ch = 0; ch < NCH; ch++) {
        CP_WAIT2();
        __syncthreads();

        if (ch + NSTAGE - 1 < NCH) {
            const uint32_t sb = s0 + (uint32_t)((ch + NSTAGE - 1) & (NSTAGE - 1)) * STAGE_B;
            CP_ASYNC16(sb + cdst,          gA + (ch + NSTAGE - 1) * 32);
            CP_ASYNC16(sb + TILE_B + cdst, gW + (ch + NSTAGE - 1) * 32);
        }
        CP_COMMIT();

        const uint32_t cur = s0 + (uint32_t)(ch & (NSTAGE - 1)) * STAGE_B;
        const uint32_t cA = cur, cW = cur + TILE_B;

        uint32_t av0[2][4], wv0[2][4], av1[2][4], wv1[2][4];
        LDSM4(av0[0], cA + a_off);
        LDSM4(av0[1], cA + a_off + 16 * ROWB);
        LDSM4(wv0[0], cW + w_off);
        LDSM4(wv0[1], cW + w_off + 16 * ROWB);
        LDSM4(av1[0], cA + a_off + 32);
        LDSM4(av1[1], cA + a_off + 16 * ROWB + 32);
        LDSM4(wv1[0], cW + w_off + 32);
        LDSM4(wv1[1], cW + w_off + 16 * ROWB + 32);

#pragma unroll
        for (int mt = 0; mt < 2; mt++)
#pragma unroll
            for (int nt = 0; nt < 4; nt++)
                MMA16816F16(acc[mt][nt], av0[mt], (&wv0[nt >> 1][(nt & 1) * 2]));
#pragma unroll
        for (int mt = 0; mt < 2; mt++)
#pragma unroll
            for (int nt = 0; nt < 4; nt++)
                MMA16816F16(acc[mt][nt], av1[mt], (&wv1[nt >> 1][(nt & 1) * 2]));
    }

    // Epilogue
    const int er0 = bm + wm + (lane >> 2);
    const int ec0 = bn + wn + (lane & 3) * 2;

    float2 bb[4];
#pragma unroll
    for (int nt = 0; nt < 4; nt++)
        bb[nt] = *(const float2*)&bias[ec0 + nt * 8];

#pragma unroll
    for (int mt = 0; mt < 2; mt++) {
#pragma unroll
        for (int nt = 0; nt < 4; nt++) {
#pragma unroll
            for (int h = 0; h < 2; h++) {
                float2 v;
                v.x = acc[mt][nt][h * 2 + 0] + bb[nt].x;
                v.y = acc[mt][nt][h * 2 + 1] + bb[nt].y;
                const size_t idx = (size_t)(er0 + mt * 16 + h * 8) * D_ + ec0 + nt * 8;
                if (SIG) {
                    v.x = 1.f / (1.f + __expf(-v.x));
                    v.y = 1.f / (1.f + __expf(-v.y));
                    *(float2*)((float*)Cv + idx) = v;
                } else {
                    uint32_t hv = f2h(v.x, v.y);
                    *(uint32_t*)((__half*)Cv + idx) = hv;
                }
            }
        }
    }
}

__global__ void __launch_bounds__(512) gemm_qkv(
    const __half* A0, const __half* W0, const float* b0, __half* C0,
    const __half* A1, const __half* W1, const float* b1, __half* C1,
    const __half* A2, const __half* W2, const float* b2, __half* C2)
{
    extern __shared__ __align__(128) char dsm[];
    const unsigned z = blockIdx.z;
    const __half* A = (z == 0) ? A0 : (z == 1) ? A1 : A2;
    const __half* W = (z == 0) ? W0 : (z == 1) ? W1 : W2;
    const float*  b = (z == 0) ? b0 : (z == 1) ? b1 : b2;
    __half*       C = (z == 0) ? C0 : (z == 1) ? C1 : C2;
    gemm_body<0>(A, W, b, C, dsm);
}

__global__ void __launch_bounds__(512) gemm_o(
    const __half* __restrict__ A, const __half* __restrict__ W,
    const float* __restrict__ bias, float* __restrict__ C)
{
    extern __shared__ __align__(128) char dsm[];
    gemm_body<1>(A, W, bias, C, dsm);
}

// ---------------------------------------------------------------------------
// Fused "attention" middle stage, fp16 smem storage / fp32 compute.
// 512 threads, b-split warp-groups (tg0: b 0-3, tg1: b 4-7).
// smem bytes: ES (fp16) [0, 69632) = 8 x 64 x 68 halves
//             R region  [69632, 105472):
//               pass1: Q | K fp16 (8x1024 each = 32768 B)
//               then:  P fp32 denominator strip [0,17408) of R
//               then:  V fp16 at R+17408 (8 x 16 x 72 halves = 18432 B)
// All LDS halved vs fp32 version -> smem-bandwidth-bound kernel ~2x faster.
// ---------------------------------------------------------------------------
#define ESH_STRIDE 68
#define ESH_PER_B  (64 * ESH_STRIDE)         // 4352 halves
#define VH_STRIDE  72
#define VH_PER_B   (16 * VH_STRIDE)          // 1152 halves
#define ES_BYTES   (8 * ESH_PER_B * 2)       // 69632
#define V_OFF      17408                     // byte offset of V inside R
#define ATTN_SMEM  (ES_BYTES + V_OFF + 8 * VH_PER_B * 2)   // 105472

__global__ void __launch_bounds__(512) attn_kernel()
{
    extern __shared__ __align__(16) char asmb[];
    __half* ES = (__half*)asmb;
    __half* Rh = (__half*)(asmb + ES_BYTES);          // Q|K during pass1
    float*  P  = (float*)(asmb + ES_BYTES);           // denom strip (reuse)
    __half* Vh = (__half*)(asmb + ES_BYTES + V_OFF);  // V (reuse, disjoint from P)

    const int s  = blockIdx.x;
    const int t  = threadIdx.x;
    const int tg = t >> 8;
    const int tt = t & 255;

    const __half* Qg = (const __half*)g_Q;
    const __half* Kg = (const __half*)g_K;
    const __half* Vg = (const __half*)g_V;

    // Load Q,K (fp16) for all 8 batches at this s: 1024 uint4 each
    for (int f = t; f < 1024; f += 512) {
        const int b  = f >> 7;
        const int d8 = f & 127;
        const size_t g = ((size_t)b * S_ + s) * 128 + d8;
        ((uint4*)Rh)[f]          = ((const uint4*)Qg)[g];
        ((uint4*)(Rh + 8192))[f] = ((const uint4*)Kg)[g];
    }
    __syncthreads();

    const int tp = (tt >> 4) * 4;
    const int tq = (tt & 15) * 4;
    const int b0 = tg * 4;

    float sacc[4][4];
#pragma unroll
    for (int i = 0; i < 4; i++)
#pragma unroll
        for (int j = 0; j < 4; j++) sacc[i][j] = 0.f;

    // Pass 1: exp-scores (fp32 math from fp16 Q/K), fp16 ES store
#pragma unroll
    for (int bb = 0; bb < 4; bb++) {
        const int b = b0 + bb;
        const __half* Qb = Rh + b * 1024;
        const __half* Kb = Rh + 8192 + b * 1024;
        float acc[4][4];
#pragma unroll
        for (int i = 0; i < 4; i++)
#pragma unroll
            for (int j = 0; j < 4; j++) acc[i][j] = 0.f;

#pragma unroll
        for (int h = 0; h < 16; h++) {
            uint2 qv = *(const uint2*)(Qb + h * 64 + tp);
            uint2 kv = *(const uint2*)(Kb + h * 64 + tq);
            float2 q01 = h2f(qv.x), q23 = h2f(qv.y);
            float2 k01 = h2f(kv.x), k23 = h2f(kv.y);
            float qa[4] = {q01.x, q01.y, q23.x, q23.y};
            float ka[4] = {k01.x, k01.y, k23.x, k23.y};
#pragma unroll
            for (int i = 0; i < 4; i++)
#pragma unroll
                for (int j = 0; j < 4; j++)
                    acc[i][j] += qa[i] * ka[j];
        }
        __half* ESb = ES + b * ESH_PER_B;
#pragma unroll
        for (int i = 0; i < 4; i++) {
            float e0 = __expf(acc[i][0] * 0.125f);
            float e1 = __expf(acc[i][1] * 0.125f);
            float e2 = __expf(acc[i][2] * 0.125f);
            float e3 = __expf(acc[i][3] * 0.125f);
            sacc[i][0] += e0; sacc[i][1] += e1;
            sacc[i][2] += e2; sacc[i][3] += e3;
            *(uint2*)(ESb + (tp + i) * ESH_STRIDE + tq) =
                make_uint2(f2h(e0, e1), f2h(e2, e3));
        }
    }
    __syncthreads();   // Q/K dead; R reusable as P strip

    // Denominator exchange between the two warp-groups via P (fp32)
    if (tg == 0) {
#pragma unroll
        for (int i = 0; i < 4; i++)
            *(float4*)&P[(tp + i) * ESH_STRIDE + tq] =
                make_float4(sacc[i][0], sacc[i][1], sacc[i][2], sacc[i][3]);
    }
    __syncthreads();

    float rd[4][4];
    if (tg == 1) {
#pragma unroll
        for (int i = 0; i < 4; i++) {
            float4 o = *(const float4*)&P[(tp + i) * ESH_STRIDE + tq];
            rd[i][0] = 1.f / (o.x + sacc[i][0]);
            rd[i][1] = 1.f / (o.y + sacc[i][1]);
            rd[i][2] = 1.f / (o.z + sacc[i][2]);
            rd[i][3] = 1.f / (o.w + sacc[i][3]);
        }
        __syncthreads();
#pragma unroll
        for (int i = 0; i < 4; i++)
            *(float4*)&P[(tp + i) * ESH_STRIDE + tq] =
                make_float4(rd[i][0], rd[i][1], rd[i][2], rd[i][3]);
    } else {
        __syncthreads();
    }
    __syncthreads();
    if (tg == 0) {
#pragma unroll
        for (int i = 0; i < 4; i++) {
            float4 r4 = *(const float4*)&P[(tp + i) * ESH_STRIDE + tq];
            rd[i][0] = r4.x; rd[i][1] = r4.y; rd[i][2] = r4.z; rd[i][3] = r4.w;
        }
    }

    // Normalize this group's ES in place (fp16 <-> fp32)
#pragma unroll
    for (int bb = 0; bb < 4; bb++) {
        __half* ESb = ES + (b0 + bb) * ESH_PER_B;
#pragma unroll
        for (int i = 0; i < 4; i++) {
            uint2 ev = *(const uint2*)(ESb + (tp + i) * ESH_STRIDE + tq);
            float2 e01 = h2f(ev.x), e23 = h2f(ev.y);
            *(uint2*)(ESb + (tp + i) * ESH_STRIDE + tq) =
                make_uint2(f2h(e01.x * rd[i][0], e01.y * rd[i][1]),
                           f2h(e23.x * rd[i][2], e23.y * rd[i][3]));
        }
    }

    // Load V (fp16, stride-72 padded). V region disjoint from P.
    for (int f = t; f < 1024; f += 512) {
        const int b  = f >> 7;
        const int d8 = f & 127;
        const size_t g = ((size_t)b * S_ + s) * 128 + d8;
        uint4 v = ((const uint4*)Vg)[g];
        const int d = d8 * 8;
        const int h = d >> 6;
        const int q = d & 63;
        *(uint4*)(Vh + b * VH_PER_B + h * VH_STRIDE + q) = v;
    }
    __syncthreads();

    // Pass 2 register-tiled: 64 threads per b, 4h x 4p outputs each.
    {
        const int bsel = tt >> 6;
        const int u    = tt & 63;
        const int lp   = u & 15;
        const int lh   = u >> 4;
        const int b    = b0 + bsel;
        const __half* ESb = ES + b * ESH_PER_B;
        const __half* Vb  = Vh + b * VH_PER_B;

        float oacc[4][4];
#pragma unroll
        for (int i = 0; i < 4; i++)
#pragma unroll
            for (int j = 0; j < 4; j++) oacc[i][j] = 0.f;

#pragma unroll
        for (int q = 0; q < 64; q += 4) {
            float2 e0[4], e1[4], v0[4], v1[4];
#pragma unroll
            for (int pp = 0; pp < 4; pp++) {
                uint2 ev = *(const uint2*)(ESb + (lp + 16 * pp) * ESH_STRIDE + q);
                e0[pp] = h2f(ev.x); e1[pp] = h2f(ev.y);
            }
#pragma unroll
            for (int hh = 0; hh < 4; hh++) {
                uint2 vv = *(const uint2*)(Vb + (lh + 4 * hh) * VH_STRIDE + q);
                v0[hh] = h2f(vv.x); v1[hh] = h2f(vv.y);
            }
#pragma unroll
            for (int hh = 0; hh < 4; hh++)
#pragma unroll
                for (int pp = 0; pp < 4; pp++)
                    oacc[hh][pp] += e0[pp].x * v0[hh].x + e0[pp].y * v0[hh].y +
                                    e1[pp].x * v1[hh].x + e1[pp].y * v1[hh].y;
        }

        __half* ob = g_a16 + ((size_t)b * S_ + s) * D_;
#pragma unroll
        for (int hh = 0; hh < 4; hh++)
#pragma unroll
            for (int pp = 0; pp < 4; pp++)
                ob[(lh + 4 * hh) * 64 + lp + 16 * pp] = __float2half(oacc[hh][pp]);
    }
}

// ---------------------------------------------------------------------------
extern "C" void kernel_launch(void* const* d_in, const int* in_sizes, int n_in,
                              void* d_out, int out_size)
{
    const float* query = (const float*)d_in[0];
    const float* key   = (const float*)d_in[1];
    const float* value = (const float*)d_in[2];
    const float* Wq    = (const float*)d_in[3];
    const float* bq    = (const float*)d_in[4];
    const float* Wk    = (const float*)d_in[5];
    const float* bk    = (const float*)d_in[6];
    const float* Wv    = (const float*)d_in[7];
    const float* bv    = (const float*)d_in[8];
    const float* Wo    = (const float*)d_in[9];
    const float* bo    = (const float*)d_in[10];
    float* out = (float*)d_out;

    float *gQ, *gK, *gV;
    __half *q16, *k16, *v16, *a16, *wq16, *wk16, *wv16, *wo16;
    cudaGetSymbolAddress((void**)&gQ, g_Q);
    cudaGetSymbolAddress((void**)&gK, g_K);
    cudaGetSymbolAddress((void**)&gV, g_V);
    cudaGetSymbolAddress((void**)&q16, g_q16);
    cudaGetSymbolAddress((void**)&k16, g_k16);
    cudaGetSymbolAddress((void**)&v16, g_v16);
    cudaGetSymbolAddress((void**)&a16, g_a16);
    cudaGetSymbolAddress((void**)&wq16, g_wq16);
    cudaGetSymbolAddress((void**)&wk16, g_wk16);
    cudaGetSymbolAddress((void**)&wv16, g_wv16);
    cudaGetSymbolAddress((void**)&wo16, g_wo16);

    // Pre-convert inputs + weights to fp16
    const int nIn4 = (M_TOT * D_) / 4;
    const int nW4  = (D_ * D_) / 4;
    cvt16<<<(nIn4 + 255) / 256, 256>>>((const float4*)query, (uint2*)q16, nIn4);
    cvt16<<<(nIn4 + 255) / 256, 256>>>((const float4*)key,   (uint2*)k16, nIn4);
    cvt16<<<(nIn4 + 255) / 256, 256>>>((const float4*)value, (uint2*)v16, nIn4);
    cvt16<<<(nW4 + 255) / 256, 256>>>((const float4*)Wq, (uint2*)wq16, nW4);
    cvt16<<<(nW4 + 255) / 256, 256>>>((const float4*)Wk, (uint2*)wk16, nW4);
    cvt16<<<(nW4 + 255) / 256, 256>>>((const float4*)Wv, (uint2*)wv16, nW4);
    cvt16<<<(nW4 + 255) / 256, 256>>>((const float4*)Wo, (uint2*)wo16, nW4);

    cudaFuncSetAttribute(gemm_qkv,
                         cudaFuncAttributeMaxDynamicSharedMemorySize, GEMM_SMEM);
    cudaFuncSetAttribute(gemm_o,
                         cudaFuncAttributeMaxDynamicSharedMemorySize, GEMM_SMEM);
    cudaFuncSetAttribute(attn_kernel,
                         cudaFuncAttributeMaxDynamicSharedMemorySize, ATTN_SMEM);

    // Merged Q/K/V projection writing fp16 outputs
    {
        dim3 grid(D_ / 128, M_TOT / 128, 3);   // (8, 64, 3)
        gemm_qkv<<<grid, 512, GEMM_SMEM>>>(
            q16, wq16, bq, (__half*)gQ,
            k16, wk16, bk, (__half*)gK,
            v16, wv16, bv, (__half*)gV);
    }

    attn_kernel<<<S_, 512, ATTN_SMEM>>>();

    {
        dim3 grid(D_ / 128, M_TOT / 128);      // (8, 64)
        gemm_o<<<grid, 512, GEMM_SMEM>>>(a16, wo16, bo, out);
    }
}

// round 13
// speedup vs baseline: 1.3724x; 1.1297x over previous
#include <cuda_runtime.h>
#include <cuda_fp16.h>
#include <cstdint>

// Problem constants
#define B_ 8
#define S_ 1024
#define D_ 1024
#define M_TOT (B_ * S_)   // 8192

// Scratch (allocation-free rule: __device__ globals)
// g_Q/g_K/g_V sized as float but used as fp16 (half the space).
__device__ float  g_Q[B_ * S_ * D_];
__device__ float  g_K[B_ * S_ * D_];
__device__ float  g_V[B_ * S_ * D_];
__device__ __half g_q16[B_ * S_ * D_];
__device__ __half g_k16[B_ * S_ * D_];
__device__ __half g_v16[B_ * S_ * D_];
__device__ __half g_a16[B_ * S_ * D_];
__device__ __half g_wq16[D_ * D_];
__device__ __half g_wk16[D_ * D_];
__device__ __half g_wv16[D_ * D_];
__device__ __half g_wo16[D_ * D_];

// ---------------------------------------------------------------------------
// Helpers
// ---------------------------------------------------------------------------
__device__ __forceinline__ uint32_t smem_u32(const void* p) {
    uint32_t a;
    asm("{ .reg .u64 t; cvta.to.shared.u64 t, %1; cvt.u32.u64 %0, t; }"
        : "=r"(a) : "l"(p));
    return a;
}

__device__ __forceinline__ float2 h2f(uint32_t h) {
    __half2 hh = *(__half2*)&h;
    return __half22float2(hh);
}
__device__ __forceinline__ uint32_t f2h(float lo, float hi) {
    uint32_t r;
    asm("cvt.rn.f16x2.f32 %0, %1, %2;" : "=r"(r) : "f"(hi), "f"(lo));
    return r;
}

#define LDSM4(r, addr)                                                        \
    asm volatile("ldmatrix.sync.aligned.m8n8.x4.shared.b16 "                  \
                 "{%0, %1, %2, %3}, [%4];"                                    \
                 : "=r"((r)[0]), "=r"((r)[1]), "=r"((r)[2]), "=r"((r)[3])     \
                 : "r"(addr))

#define LDSM4T(r, addr)                                                       \
    asm volatile("ldmatrix.sync.aligned.m8n8.x4.trans.shared.b16 "            \
                 "{%0, %1, %2, %3}, [%4];"                                    \
                 : "=r"((r)[0]), "=r"((r)[1]), "=r"((r)[2]), "=r"((r)[3])     \
                 : "r"(addr))

#define MMA16816F16(d, a, b)                                                  \
    asm volatile("mma.sync.aligned.m16n8k16.row.col.f32.f16.f16.f32 "         \
                 "{%0, %1, %2, %3}, {%4, %5, %6, %7}, {%8, %9}, "             \
                 "{%0, %1, %2, %3};"                                          \
                 : "+f"((d)[0]), "+f"((d)[1]), "+f"((d)[2]), "+f"((d)[3])     \
                 : "r"((a)[0]), "r"((a)[1]), "r"((a)[2]), "r"((a)[3]),        \
                   "r"((b)[0]), "r"((b)[1]))

#define CP_ASYNC16(dst, src)                                                  \
    asm volatile("cp.async.cg.shared.global [%0], [%1], 16;"                  \
                 :: "r"(dst), "l"(src) : "memory")
#define CP_COMMIT() asm volatile("cp.async.commit_group;" ::: "memory")
#define CP_WAIT2()  asm volatile("cp.async.wait_group 2;" ::: "memory")

// ---------------------------------------------------------------------------
// fp32 -> fp16 pre-conversion
// ---------------------------------------------------------------------------
__global__ void cvt16(const float4* __restrict__ in, uint2* __restrict__ out,
                      int n4)
{
    int i = blockIdx.x * blockDim.x + threadIdx.x;
    if (i < n4) {
        float4 v = in[i];
        out[i] = make_uint2(f2h(v.x, v.y), f2h(v.z, v.w));
    }
}

// ---------------------------------------------------------------------------
// fp16 HMMA GEMM body (unchanged from R12 — at measured issue floor)
// ---------------------------------------------------------------------------
#define ROWB 80
#define TILE_B (128 * ROWB)
#define STAGE_B (2 * TILE_B)
#define NSTAGE 4
#define GEMM_SMEM (NSTAGE * STAGE_B)  // 81920 bytes
#define NCH (D_ / 32)

template <int SIG>
__device__ __forceinline__ void gemm_body(
    const __half* __restrict__ A, const __half* __restrict__ W,
    const float* __restrict__ bias, void* __restrict__ Cv, char* dsm)
{
    const uint32_t s0 = smem_u32(dsm);

    const int t    = threadIdx.x;
    const int warp = t >> 5;
    const int lane = t & 31;
    const int bm   = blockIdx.y * 128;
    const int bn   = blockIdx.x * 128;
    const int wm   = (warp & 3) * 32;
    const int wn   = (warp >> 2) * 32;

    const int crow = t >> 2;
    const int cseg = t & 3;
    const __half* gA = A + (size_t)(bm + crow) * D_ + cseg * 8;
    const __half* gW = W + (size_t)(bn + crow) * D_ + cseg * 8;
    const uint32_t cdst = (uint32_t)crow * ROWB + cseg * 16;

    const uint32_t a_off = (uint32_t)(wm + (lane & 15)) * ROWB + ((lane >> 4) << 4);
    const uint32_t w_off =
        (uint32_t)(wn + ((lane >> 4) << 3) + (lane & 7)) * ROWB + (((lane >> 3) & 1) << 4);

    float acc[2][4][4];
#pragma unroll
    for (int mt = 0; mt < 2; mt++)
#pragma unroll
        for (int nt = 0; nt < 4; nt++)
#pragma unroll
            for (int i = 0; i < 4; i++) acc[mt][nt][i] = 0.f;

#pragma unroll
    for (int st = 0; st < NSTAGE - 1; st++) {
        const uint32_t sb = s0 + st * STAGE_B;
        CP_ASYNC16(sb + cdst,          gA + st * 32);
        CP_ASYNC16(sb + TILE_B + cdst, gW + st * 32);
        CP_COMMIT();
    }

#pragma unroll 1
    for (int ch = 0; ch < NCH; ch++) {
        CP_WAIT2();
        __syncthreads();

        if (ch + NSTAGE - 1 < NCH) {
            const uint32_t sb = s0 + (uint32_t)((ch + NSTAGE - 1) & (NSTAGE - 1)) * STAGE_B;
            CP_ASYNC16(sb + cdst,          gA + (ch + NSTAGE - 1) * 32);
            CP_ASYNC16(sb + TILE_B + cdst, gW + (ch + NSTAGE - 1) * 32);
        }
        CP_COMMIT();

        const uint32_t cur = s0 + (uint32_t)(ch & (NSTAGE - 1)) * STAGE_B;
        const uint32_t cA = cur, cW = cur + TILE_B;

        uint32_t av0[2][4], wv0[2][4], av1[2][4], wv1[2][4];
        LDSM4(av0[0], cA + a_off);
        LDSM4(av0[1], cA + a_off + 16 * ROWB);
        LDSM4(wv0[0], cW + w_off);
        LDSM4(wv0[1], cW + w_off + 16 * ROWB);
        LDSM4(av1[0], cA + a_off + 32);
        LDSM4(av1[1], cA + a_off + 16 * ROWB + 32);
        LDSM4(wv1[0], cW + w_off + 32);
        LDSM4(wv1[1], cW + w_off + 16 * ROWB + 32);

#pragma unroll
        for (int mt = 0; mt < 2; mt++)
#pragma unroll
            for (int nt = 0; nt < 4; nt++)
                MMA16816F16(acc[mt][nt], av0[mt], (&wv0[nt >> 1][(nt & 1) * 2]));
#pragma unroll
        for (int mt = 0; mt < 2; mt++)
#pragma unroll
            for (int nt = 0; nt < 4; nt++)
                MMA16816F16(acc[mt][nt], av1[mt], (&wv1[nt >> 1][(nt & 1) * 2]));
    }

    const int er0 = bm + wm + (lane >> 2);
    const int ec0 = bn + wn + (lane & 3) * 2;

    float2 bb[4];
#pragma unroll
    for (int nt = 0; nt < 4; nt++)
        bb[nt] = *(const float2*)&bias[ec0 + nt * 8];

#pragma unroll
    for (int mt = 0; mt < 2; mt++) {
#pragma unroll
        for (int nt = 0; nt < 4; nt++) {
#pragma unroll
            for (int h = 0; h < 2; h++) {
                float2 v;
                v.x = acc[mt][nt][h * 2 + 0] + bb[nt].x;
                v.y = acc[mt][nt][h * 2 + 1] + bb[nt].y;
                const size_t idx = (size_t)(er0 + mt * 16 + h * 8) * D_ + ec0 + nt * 8;
                if (SIG) {
                    v.x = 1.f / (1.f + __expf(-v.x));
                    v.y = 1.f / (1.f + __expf(-v.y));
                    *(float2*)((float*)Cv + idx) = v;
                } else {
                    *(uint32_t*)((__half*)Cv + idx) = f2h(v.x, v.y);
                }
            }
        }
    }
}

__global__ void __launch_bounds__(512) gemm_qkv(
    const __half* A0, const __half* W0, const float* b0, __half* C0,
    const __half* A1, const __half* W1, const float* b1, __half* C1,
    const __half* A2, const __half* W2, const float* b2, __half* C2)
{
    extern __shared__ __align__(128) char dsm[];
    const unsigned z = blockIdx.z;
    const __half* A = (z == 0) ? A0 : (z == 1) ? A1 : A2;
    const __half* W = (z == 0) ? W0 : (z == 1) ? W1 : W2;
    const float*  b = (z == 0) ? b0 : (z == 1) ? b1 : b2;
    __half*       C = (z == 0) ? C0 : (z == 1) ? C1 : C2;
    gemm_body<0>(A, W, b, C, dsm);
}

__global__ void __launch_bounds__(512) gemm_o(
    const __half* __restrict__ A, const __half* __restrict__ W,
    const float* __restrict__ bias, float* __restrict__ C)
{
    extern __shared__ __align__(128) char dsm[];
    gemm_body<1>(A, W, bias, C, dsm);
}

// ---------------------------------------------------------------------------
// HMMA attention middle stage. 256 threads (8 warps), one CTA per s.
//
// Pass 1 (scores): per b, C[64p,64q] = Q'[64,16] x K'[64,16]^T, one K=16 step.
//   Q,K staged as [b][h][p] rows (144B stride); A/B fragments via
//   ldmatrix.trans (col-major recipe). Warp w owns p-tile (w&3), q-half
//   (w>>2) for ALL 8 batches -> exp + batch-denominator purely in registers.
//   Unnormalized exp stored fp16 to ES[b][p][q] (144B rows), then normalized
//   in place by the owning warp (warp-private, no barrier).
//
// Pass 2 (AV): warp w handles b=w: C[16h,64p] = V[16h,64q] x ES[64p,64q]^T,
//   non-trans ldmatrix exactly like the GEMM. C cols = p -> contiguous
//   uint32 stores to g_a16 (d = h*64+p).
// ---------------------------------------------------------------------------
#define QRS 144                       // Q/K/V row stride bytes (64 halves+pad)
#define QB_BYTES (16 * QRS)           // 2304 per batch
#define ESRS 144                      // ES row stride bytes
#define ESB_BYTES (64 * ESRS)         // 9216 per batch
#define ES_TOT (8 * ESB_BYTES)        // 73728
#define Q_OFF  ES_TOT                 // 73728
#define K_OFF  (Q_OFF + 8 * QB_BYTES) // 92160
#define ATTN_SMEM (K_OFF + 8 * QB_BYTES)  // 110592

__global__ void __launch_bounds__(256) attn_kernel()
{
    extern __shared__ __align__(16) char asmb[];
    const uint32_t sb = smem_u32(asmb);
    const uint32_t ES0 = sb;
    const uint32_t Q0  = sb + Q_OFF;
    const uint32_t K0  = sb + K_OFF;
    const uint32_t V0  = Q0;              // V reuses Q region after pass 1

    const int s    = blockIdx.x;
    const int t    = threadIdx.x;
    const int w    = t >> 5;
    const int lane = t & 31;

    const __half* Qg = (const __half*)g_Q;
    const __half* Kg = (const __half*)g_K;
    const __half* Vg = (const __half*)g_V;

    // ---- Load Q,K into [b][h][p] rows (uint4 = 8 p at one h, direct copy)
    for (int u = t; u < 2048; u += 256) {
        const int isK  = u >> 10;
        const int v    = u & 1023;
        const int b    = v >> 7;
        const int h    = (v & 127) >> 3;
        const int pseg = v & 7;
        const size_t gi = ((size_t)b * S_ + s) * 128 + h * 8 + pseg;
        uint4 val = isK ? ((const uint4*)Kg)[gi] : ((const uint4*)Qg)[gi];
        char* dst = asmb + (isK ? K_OFF : Q_OFF) + b * QB_BYTES + h * QRS + pseg * 16;
        *(uint4*)dst = val;
    }
    __syncthreads();

    // ---- Pass 1
    const int p0 = (w & 3) * 16;
    const int q0 = (w >> 2) * 32;

    // trans-ldmatrix lane addressing
    const uint32_t krA  = (uint32_t)((lane & 7) + ((lane >> 4) << 3));  // A k-row
    const uint32_t caA  = (uint32_t)(p0 + ((lane >> 3) & 1) * 8) * 2;   // A m-col
    const uint32_t krB  = (uint32_t)((lane & 7) + ((lane >> 3) & 1) * 8);
    const uint32_t cbB  = (uint32_t)((lane >> 4) * 8) * 2;              // B n-col part

    const int row0 = p0 + (lane >> 2);
    const int colq = q0 + (lane & 3) * 2;

    float denom[4][4];
#pragma unroll
    for (int nt = 0; nt < 4; nt++)
#pragma unroll
        for (int i = 0; i < 4; i++) denom[nt][i] = 0.f;

#pragma unroll 1
    for (int b = 0; b < 8; b++) {
        const uint32_t Qb = Q0 + b * QB_BYTES;
        const uint32_t Kb = K0 + b * QB_BYTES;
        char* ESp = asmb + b * ESB_BYTES;

        uint32_t afr[4];
        LDSM4T(afr, Qb + krA * QRS + caA);
        uint32_t bfr[2][4];
        LDSM4T(bfr[0], Kb + krB * QRS + (uint32_t)q0 * 2 + cbB);
        LDSM4T(bfr[1], Kb + krB * QRS + (uint32_t)(q0 + 16) * 2 + cbB);

        float acc[4][4];
#pragma unroll
        for (int nt = 0; nt < 4; nt++)
#pragma unroll
            for (int i = 0; i < 4; i++) acc[nt][i] = 0.f;
#pragma unroll
        for (int nt = 0; nt < 4; nt++)
            MMA16816F16(acc[nt], afr, (&bfr[nt >> 1][(nt & 1) * 2]));

#pragma unroll
        for (int nt = 0; nt < 4; nt++) {
            float e0 = __expf(acc[nt][0] * 0.125f);
            float e1 = __expf(acc[nt][1] * 0.125f);
            float e2 = __expf(acc[nt][2] * 0.125f);
            float e3 = __expf(acc[nt][3] * 0.125f);
            denom[nt][0] += e0; denom[nt][1] += e1;
            denom[nt][2] += e2; denom[nt][3] += e3;
            *(uint32_t*)(ESp + row0 * ESRS + (colq + nt * 8) * 2)       = f2h(e0, e1);
            *(uint32_t*)(ESp + (row0 + 8) * ESRS + (colq + nt * 8) * 2) = f2h(e2, e3);
        }
    }

    float rd[4][4];
#pragma unroll
    for (int nt = 0; nt < 4; nt++)
#pragma unroll
        for (int i = 0; i < 4; i++) rd[nt][i] = 1.f / denom[nt][i];

    __syncthreads();   // all Q/K reads done -> V may overwrite Q region

    // ---- Load V (same layout as Q), overlapped with normalization below
    for (int u = t; u < 1024; u += 256) {
        const int b    = u >> 7;
        const int h    = (u & 127) >> 3;
        const int pseg = u & 7;
        const size_t gi = ((size_t)b * S_ + s) * 128 + h * 8 + pseg;
        uint4 val = ((const uint4*)Vg)[gi];
        *(uint4*)(asmb + Q_OFF + b * QB_BYTES + h * QRS + pseg * 16) = val;
    }

    // ---- Normalize own ES cells (warp-private stores; no barrier needed)
#pragma unroll 1
    for (int b = 0; b < 8; b++) {
        char* ESp = asmb + b * ESB_BYTES;
#pragma unroll
        for (int nt = 0; nt < 4; nt++) {
            uint32_t* a0 = (uint32_t*)(ESp + row0 * ESRS + (colq + nt * 8) * 2);
            uint32_t* a1 = (uint32_t*)(ESp + (row0 + 8) * ESRS + (colq + nt * 8) * 2);
            float2 v0 = h2f(*a0), v1 = h2f(*a1);
            *a0 = f2h(v0.x * rd[nt][0], v0.y * rd[nt][1]);
            *a1 = f2h(v1.x * rd[nt][2], v1.y * rd[nt][3]);
        }
    }
    __syncthreads();   // V visible; all warps' ES normalized

    // ---- Pass 2: warp w handles batch b = w
    {
        const uint32_t Vb  = V0 + (uint32_t)w * QB_BYTES;
        const uint32_t ESb = ES0 + (uint32_t)w * ESB_BYTES;

        const uint32_t aoff = (uint32_t)(lane & 15) * QRS + ((lane >> 4) << 4);
        const uint32_t boff = (uint32_t)(((lane >> 4) << 3) + (lane & 7)) * ESRS +
                              (((lane >> 3) & 1) << 4);

        float acc2[8][4];
#pragma unroll
        for (int nt = 0; nt < 8; nt++)
#pragma unroll
            for (int i = 0; i < 4; i++) acc2[nt][i] = 0.f;

#pragma unroll
        for (int ks = 0; ks < 4; ks++) {
            uint32_t av[4];
            LDSM4(av, Vb + aoff + ks * 32);
            uint32_t bv[4][4];
#pragma unroll
            for (int g = 0; g < 4; g++)
                LDSM4(bv[g], ESb + boff + (uint32_t)g * 16 * ESRS + ks * 32);
#pragma unroll
            for (int nt = 0; nt < 8; nt++)
                MMA16816F16(acc2[nt], av, (&bv[nt >> 1][(nt & 1) * 2]));
        }

        // C[h][p]: pairs contiguous in d = h*64 + p
        __half* ob = g_a16 + ((size_t)w * S_ + s) * D_;
        const int hr = lane >> 2;
        const int pc = (lane & 3) * 2;
#pragma unroll
        for (int nt = 0; nt < 8; nt++) {
            *(uint32_t*)(ob + hr * 64 + nt * 8 + pc)       = f2h(acc2[nt][0], acc2[nt][1]);
            *(uint32_t*)(ob + (hr + 8) * 64 + nt * 8 + pc) = f2h(acc2[nt][2], acc2[nt][3]);
        }
    }
}

// ---------------------------------------------------------------------------
extern "C" void kernel_launch(void* const* d_in, const int* in_sizes, int n_in,
                              void* d_out, int out_size)
{
    const float* query = (const float*)d_in[0];
    const float* key   = (const float*)d_in[1];
    const float* value = (const float*)d_in[2];
    const float* Wq    = (const float*)d_in[3];
    const float* bq    = (const float*)d_in[4];
    const float* Wk    = (const float*)d_in[5];
    const float* bk    = (const float*)d_in[6];
    const float* Wv    = (const float*)d_in[7];
    const float* bv    = (const float*)d_in[8];
    const float* Wo    = (const float*)d_in[9];
    const float* bo    = (const float*)d_in[10];
    float* out = (float*)d_out;

    float *gQ, *gK, *gV;
    __half *q16, *k16, *v16, *a16, *wq16, *wk16, *wv16, *wo16;
    cudaGetSymbolAddress((void**)&gQ, g_Q);
    cudaGetSymbolAddress((void**)&gK, g_K);
    cudaGetSymbolAddress((void**)&gV, g_V);
    cudaGetSymbolAddress((void**)&q16, g_q16);
    cudaGetSymbolAddress((void**)&k16, g_k16);
    cudaGetSymbolAddress((void**)&v16, g_v16);
    cudaGetSymbolAddress((void**)&a16, g_a16);
    cudaGetSymbolAddress((void**)&wq16, g_wq16);
    cudaGetSymbolAddress((void**)&wk16, g_wk16);
    cudaGetSymbolAddress((void**)&wv16, g_wv16);
    cudaGetSymbolAddress((void**)&wo16, g_wo16);

    const int nIn4 = (M_TOT * D_) / 4;
    const int nW4  = (D_ * D_) / 4;
    cvt16<<<(nIn4 + 255) / 256, 256>>>((const float4*)query, (uint2*)q16, nIn4);
    cvt16<<<(nIn4 + 255) / 256, 256>>>((const float4*)key,   (uint2*)k16, nIn4);
    cvt16<<<(nIn4 + 255) / 256, 256>>>((const float4*)value, (uint2*)v16, nIn4);
    cvt16<<<(nW4 + 255) / 256, 256>>>((const float4*)Wq, (uint2*)wq16, nW4);
    cvt16<<<(nW4 + 255) / 256, 256>>>((const float4*)Wk, (uint2*)wk16, nW4);
    cvt16<<<(nW4 + 255) / 256, 256>>>((const float4*)Wv, (uint2*)wv16, nW4);
    cvt16<<<(nW4 + 255) / 256, 256>>>((const float4*)Wo, (uint2*)wo16, nW4);

    cudaFuncSetAttribute(gemm_qkv,
                         cudaFuncAttributeMaxDynamicSharedMemorySize, GEMM_SMEM);
    cudaFuncSetAttribute(gemm_o,
                         cudaFuncAttributeMaxDynamicSharedMemorySize, GEMM_SMEM);
    cudaFuncSetAttribute(attn_kernel,
                         cudaFuncAttributeMaxDynamicSharedMemorySize, ATTN_SMEM);

    {
        dim3 grid(D_ / 128, M_TOT / 128, 3);   // (8, 64, 3)
        gemm_qkv<<<grid, 512, GEMM_SMEM>>>(
            q16, wq16, bq, (__half*)gQ,
            k16, wk16, bk, (__half*)gK,
            v16, wv16, bv, (__half*)gV);
    }

    attn_kernel<<<S_, 256, ATTN_SMEM>>>();

    {
        dim3 grid(D_ / 128, M_TOT / 128);      // (8, 64)
        gemm_o<<<grid, 512, GEMM_SMEM>>>(a16, wo16, bo, out);
    }
}